// round 8
// baseline (speedup 1.0000x reference)
#include <cuda_runtime.h>
#include <cuda_fp16.h>
#include <math.h>
#include <stdint.h>

// ---------------------------------------------------------------------------
// Problem dims
// ---------------------------------------------------------------------------
#define D_MODEL 768
#define D_INNER 1536
#define D_STATE 16
#define DT_RANK 96
#define H_FFN   2048
#define LSEQ    2048
#define XPROJ_N 128
#define KDT_PAD 128

// ---------------------------------------------------------------------------
// Scratch
// ---------------------------------------------------------------------------
__device__ float g_lin1[LSEQ * D_INNER];   // raw in-proj, then z (in-place)
__device__ float g_lin2[LSEQ * D_INNER];   // raw gate-proj
__device__ float g_xdbl[LSEQ * XPROJ_N];
__device__ float g_dt  [LSEQ * D_INNER];
__device__ float g_x2  [LSEQ * D_MODEL];
__device__ float g_up  [LSEQ * H_FFN];
__device__ float g_gate[LSEQ * H_FFN];

// fp16 activations
__device__ __half a_h  [LSEQ * D_MODEL];
__device__ __half a_z  [LSEQ * D_INNER];
__device__ __half a_xd [LSEQ * XPROJ_N];
__device__ __half a_y  [LSEQ * D_INNER];
__device__ __half a_hf [LSEQ * D_MODEL];
__device__ __half a_v  [LSEQ * H_FFN];

// fp16 weights
__device__ __half w_in_h [D_INNER * D_MODEL];
__device__ __half w_gt_h [D_INNER * D_MODEL];
__device__ __half w_x_h  [XPROJ_N * D_INNER];
__device__ __half w_dt_h [D_INNER * KDT_PAD];
__device__ __half w_out_h[D_MODEL * D_INNER];
__device__ __half w_up_h [H_FFN * D_MODEL];
__device__ __half w_gf_h [H_FFN * D_MODEL];
__device__ __half w_dn_h [D_MODEL * H_FFN];

static __device__ __forceinline__ uint32_t smem_u32(const void* p) {
    uint32_t a;
    asm("{ .reg .u64 t; cvta.to.shared.u64 t, %1; cvt.u32.u64 %0, t; }"
        : "=r"(a) : "l"(p));
    return a;
}

#define SW128(off) ((off) ^ (((off) >> 3) & 0x70))

#define LDSM4(r, addr)                                                         \
    asm volatile("ldmatrix.sync.aligned.m8n8.x4.shared.b16 {%0,%1,%2,%3}, [%4];" \
        : "=r"((r)[0]), "=r"((r)[1]), "=r"((r)[2]), "=r"((r)[3]) : "r"(addr))

#define MMA16816(c, a, b0, b1)                                                 \
    asm volatile("mma.sync.aligned.m16n8k16.row.col.f32.f16.f16.f32 "          \
        "{%0,%1,%2,%3}, {%4,%5,%6,%7}, {%8,%9}, {%0,%1,%2,%3};"                \
        : "+f"((c)[0]), "+f"((c)[1]), "+f"((c)[2]), "+f"((c)[3])               \
        : "r"((a)[0]), "r"((a)[1]), "r"((a)[2]), "r"((a)[3]), "r"(b0), "r"(b1))

#define CP_ASYNC16(sa, ga)                                                     \
    asm volatile("{ .reg .u64 g; cvta.to.global.u64 g, %1; "                   \
                 "cp.async.cg.shared.global [%0], [g], 16; }"                  \
                 :: "r"(sa), "l"(ga))
#define CP_COMMIT()  asm volatile("cp.async.commit_group;" ::: "memory")
#define CP_WAIT1()   asm volatile("cp.async.wait_group 1;" ::: "memory")

// ---------------------------------------------------------------------------
// All-weights fp32->fp16 convert, one launch, compile-time segments (float4)
// ---------------------------------------------------------------------------
#define N_IN  (D_INNER * D_MODEL)
#define N_X   (XPROJ_N * D_INNER)
#define N_OUT (D_MODEL * D_INNER)
#define N_UP  (H_FFN * D_MODEL)
#define N_DN  (D_MODEL * H_FFN)
#define Q4(n) ((n) / 4)
#define SEG0 Q4(N_IN)
#define SEG1 (SEG0 + Q4(N_IN))
#define SEG2 (SEG1 + Q4(N_X))
#define SEG3 (SEG2 + Q4(N_OUT))
#define SEG4 (SEG3 + Q4(N_UP))
#define SEG5 (SEG4 + Q4(N_UP))
#define SEG6 (SEG5 + Q4(N_DN))

__global__ void w16_all_kernel(
    const float* __restrict__ sin,  __half* __restrict__ din,
    const float* __restrict__ sgt,  __half* __restrict__ dgt,
    const float* __restrict__ sx,   __half* __restrict__ dx,
    const float* __restrict__ sout, __half* __restrict__ dout,
    const float* __restrict__ sup,  __half* __restrict__ dup,
    const float* __restrict__ sgf,  __half* __restrict__ dgf,
    const float* __restrict__ sdn,  __half* __restrict__ ddn)
{
    int i = blockIdx.x * blockDim.x + threadIdx.x;
    if (i >= SEG6) return;
    const float* s; __half* d; int b;
    if      (i < SEG0) { s = sin;  d = din;  b = i; }
    else if (i < SEG1) { s = sgt;  d = dgt;  b = i - SEG0; }
    else if (i < SEG2) { s = sx;   d = dx;   b = i - SEG1; }
    else if (i < SEG3) { s = sout; d = dout; b = i - SEG2; }
    else if (i < SEG4) { s = sup;  d = dup;  b = i - SEG3; }
    else if (i < SEG5) { s = sgf;  d = dgf;  b = i - SEG4; }
    else               { s = sdn;  d = ddn;  b = i - SEG5; }
    float4 v = reinterpret_cast<const float4*>(s)[b];
    __half2* o = reinterpret_cast<__half2*>(d) + b * 2;
    o[0] = __floats2half2_rn(v.x, v.y);
    o[1] = __floats2half2_rn(v.z, v.w);
}

__global__ void w16_wdt_kernel(const float* __restrict__ src,
                               __half* __restrict__ dst)
{
    int i = blockIdx.x * blockDim.x + threadIdx.x;
    if (i < D_INNER * KDT_PAD) {
        int r = i / KDT_PAD, c = i % KDT_PAD;
        float v = (c < DT_RANK) ? src[r * DT_RANK + c] : 0.f;
        dst[i] = __float2half_rn(v);
    }
}

// ---------------------------------------------------------------------------
// Elementwise
// ---------------------------------------------------------------------------
__global__ void gate_kernel(float* __restrict__ lin1,
                            const float* __restrict__ lin2,
                            __half* __restrict__ zh, int n4)
{
    int i = blockIdx.x * blockDim.x + threadIdx.x;
    if (i < n4) {
        float4 a = reinterpret_cast<float4*>(lin1)[i];
        float4 g = reinterpret_cast<const float4*>(lin2)[i];
        a.x *= 1.f / (1.f + __expf(-g.x));
        a.y *= 1.f / (1.f + __expf(-g.y));
        a.z *= 1.f / (1.f + __expf(-g.z));
        a.w *= 1.f / (1.f + __expf(-g.w));
        reinterpret_cast<float4*>(lin1)[i] = a;
        __half2* o = reinterpret_cast<__half2*>(zh) + i * 2;
        o[0] = __floats2half2_rn(a.x, a.y);
        o[1] = __floats2half2_rn(a.z, a.w);
    }
}

__global__ void silu_mul_kernel(const float* __restrict__ up,
                                const float* __restrict__ gate,
                                __half* __restrict__ vh, int n4)
{
    int i = blockIdx.x * blockDim.x + threadIdx.x;
    if (i < n4) {
        float4 u = reinterpret_cast<const float4*>(up)[i];
        float4 g = reinterpret_cast<const float4*>(gate)[i];
        float4 v;
        v.x = g.x / (1.f + __expf(-g.x)) * u.x;
        v.y = g.y / (1.f + __expf(-g.y)) * u.y;
        v.z = g.z / (1.f + __expf(-g.z)) * u.z;
        v.w = g.w / (1.f + __expf(-g.w)) * u.w;
        __half2* o = reinterpret_cast<__half2*>(vh) + i * 2;
        o[0] = __floats2half2_rn(v.x, v.y);
        o[1] = __floats2half2_rn(v.z, v.w);
    }
}

__global__ void cvt16_kernel(const float* __restrict__ src,
                             __half* __restrict__ dst, int n4)
{
    int i = blockIdx.x * blockDim.x + threadIdx.x;
    if (i < n4) {
        float4 v = reinterpret_cast<const float4*>(src)[i];
        __half2* o = reinterpret_cast<__half2*>(dst) + i * 2;
        o[0] = __floats2half2_rn(v.x, v.y);
        o[1] = __floats2half2_rn(v.z, v.w);
    }
}

// ---------------------------------------------------------------------------
// RMSNorm -> fp16
// ---------------------------------------------------------------------------
__global__ __launch_bounds__(256) void rmsnorm_kernel(
    const float* __restrict__ x, const float* __restrict__ w,
    __half* __restrict__ o16)
{
    const int t = blockIdx.x;
    const float* xr = x + (size_t)t * D_MODEL;

    float ss = 0.f;
    for (int i = threadIdx.x; i < D_MODEL; i += 256) {
        float v = xr[i];
        ss = fmaf(v, v, ss);
    }
    #pragma unroll
    for (int o = 16; o > 0; o >>= 1) ss += __shfl_xor_sync(0xffffffffu, ss, o);

    __shared__ float sh[8];
    __shared__ float s_rs;
    const int lane = threadIdx.x & 31, wid = threadIdx.x >> 5;
    if (lane == 0) sh[wid] = ss;
    __syncthreads();
    if (threadIdx.x == 0) {
        float tot = 0.f;
        #pragma unroll
        for (int i = 0; i < 8; i++) tot += sh[i];
        s_rs = rsqrtf(tot * (1.0f / D_MODEL) + 1e-6f);
    }
    __syncthreads();
    const float rs = s_rs;
    for (int i = threadIdx.x; i < D_MODEL; i += 256)
        o16[(size_t)t * D_MODEL + i] = __float2half_rn(xr[i] * rs * w[i]);
}

// ---------------------------------------------------------------------------
// fp16 GEMM on mma.sync: C[M,N] = f(A[M,K] @ B[N,K]^T), fp32 accumulate.
//   BM in {128, 64}; BN=128, KC=64, 256 threads, 3-stage cp.async pipeline
//   (ONE __syncthreads per chunk; loads issued before compute).
//   op: 0 none | 1 bias+softplus | 3 acc+aux | 5 split-K atomicAdd
//   op!=5: gridDim.z==2 batches second (B2, out2) GEMM sharing A.
// ---------------------------------------------------------------------------
template<int BM>
__global__ __launch_bounds__(256) void gemm_h1(
    const __half* __restrict__ Ah,
    const __half* __restrict__ Bh_, const __half* __restrict__ B2h,
    int K, int N,
    float* __restrict__ outF_, float* __restrict__ out2F,
    __half* __restrict__ outH,
    const float* __restrict__ aux, const float* __restrict__ bias, int op)
{
    constexpr int WN  = (BM == 128) ? 2 : 4;
    constexpr int NT  = 128 / WN / 8;            // 8 or 4
    constexpr int ATB = BM * 128;                // BM rows x 64 halves x 2B
    constexpr int BTB = 128 * 128;
    constexpr int STAGE_B = ATB + BTB;

    const bool batched2 = (op != 5) && (blockIdx.z != 0);
    const __half* Bh = batched2 ? B2h : Bh_;
    float* outF = batched2 ? out2F : outF_;

    int k_begin = 0, KL = K;
    if (op == 5) { KL = K / gridDim.z; k_begin = blockIdx.z * KL; }

    extern __shared__ char smem[];
    const uint32_t sb = smem_u32(smem);
    const int tid  = threadIdx.x;
    const int lane = tid & 31;
    const int warp = tid >> 5;
    const int m0 = blockIdx.y * BM;
    const int n0 = blockIdx.x * 128;
    const int wm0 = (warp / WN) * 32;
    const int wn0 = (warp % WN) * (128 / WN);

    const int nch = KL >> 6;

    float acc[2][NT][4];
    #pragma unroll
    for (int mt = 0; mt < 2; mt++)
        #pragma unroll
        for (int nt = 0; nt < NT; nt++)
            #pragma unroll
            for (int r = 0; r < 4; r++) acc[mt][nt][r] = 0.f;

    auto load_stage = [&](int s, int ci) {
        const int k0 = k_begin + (ci << 6);
        const uint32_t sbase = sb + s * STAGE_B;
        #pragma unroll
        for (int arr = 0; arr < 2; arr++) {
            const __half* src = (arr == 0) ? Ah : Bh;
            const int r0 = (arr == 0) ? m0 : n0;
            const int nvec = ((arr == 0) ? BM : 128) * 8;
            const uint32_t abase = sbase + ((arr == 0) ? 0 : ATB);
            #pragma unroll
            for (int jj = 0; jj < nvec / 256; jj++) {
                const int idx = jj * 256 + tid;
                const int row = idx >> 3;
                const int c16 = idx & 7;
                const __half* g = src + (size_t)(r0 + row) * K + k0 + c16 * 8;
                const uint32_t sa = abase + SW128((uint32_t)(row * 128 + c16 * 16));
                CP_ASYNC16(sa, g);
            }
        }
    };

    const int arow = ((lane >> 3) & 1) * 8 + (lane & 7);
    const int akb  = (lane >> 4) * 16;
    const int brow = ((lane >> 4) & 1) * 8 + (lane & 7);
    const int bkb  = ((lane >> 3) & 1) * 16;

    auto compute = [&](int s) {
        const uint32_t sA = sb + s * STAGE_B;
        const uint32_t sB = sA + ATB;
        #pragma unroll
        for (int ks = 0; ks < 4; ks++) {
            uint32_t a_h[2][4], b_h[NT / 2][4];
            #pragma unroll
            for (int mt = 0; mt < 2; mt++) {
                const uint32_t off = SW128(
                    (uint32_t)((wm0 + mt * 16 + arow) * 128 + ks * 32 + akb));
                LDSM4(a_h[mt], sA + off);
            }
            #pragma unroll
            for (int j = 0; j < NT / 2; j++) {
                const uint32_t off = SW128(
                    (uint32_t)((wn0 + j * 16 + brow) * 128 + ks * 32 + bkb));
                LDSM4(b_h[j], sB + off);
            }
            #pragma unroll
            for (int mt = 0; mt < 2; mt++)
                #pragma unroll
                for (int nt = 0; nt < NT; nt++) {
                    const uint32_t bh0 = b_h[nt >> 1][(nt & 1) * 2];
                    const uint32_t bh1 = b_h[nt >> 1][(nt & 1) * 2 + 1];
                    MMA16816(acc[mt][nt], a_h[mt], bh0, bh1);
                }
        }
    };

    // ---- 3-stage pipeline, one sync per chunk ----
    load_stage(0, 0); CP_COMMIT();
    if (nch > 1) { load_stage(1, 1); CP_COMMIT(); }
    int cs = 0, ls = 2;
    for (int i = 0; i < nch; i++) {
        CP_WAIT1();
        __syncthreads();
        if (i + 2 < nch) {
            load_stage(ls, i + 2); CP_COMMIT();
            ls = (ls == 2) ? 0 : ls + 1;
        }
        compute(cs);
        cs = (cs == 2) ? 0 : cs + 1;
    }
    __syncthreads();

    // epilogue via smem for coalesced stores
    float* smC = reinterpret_cast<float*>(smem);   // [BM][132]
    #pragma unroll
    for (int mt = 0; mt < 2; mt++)
        #pragma unroll
        for (int nt = 0; nt < NT; nt++) {
            const int row = wm0 + mt * 16 + (lane >> 2);
            const int col = wn0 + nt * 8 + (lane & 3) * 2;
            *reinterpret_cast<float2*>(&smC[row * 132 + col]) =
                make_float2(acc[mt][nt][0], acc[mt][nt][1]);
            *reinterpret_cast<float2*>(&smC[(row + 8) * 132 + col]) =
                make_float2(acc[mt][nt][2], acc[mt][nt][3]);
        }
    __syncthreads();

    #pragma unroll 4
    for (int e = tid; e < BM * 128; e += 256) {
        const int row = e >> 7, col = e & 127;
        float v = smC[row * 132 + col];
        const size_t ro = (size_t)(m0 + row) * N + (n0 + col);
        if (op == 1) {
            v += bias[n0 + col];
            v = (v > 20.f) ? v : log1pf(__expf(v));
        } else if (op == 3) {
            v += aux[ro];
        } else if (op == 5) {
            atomicAdd(&outF[ro], v);
            continue;
        }
        if (outF) outF[ro] = v;
        if (outH) outH[ro] = __float2half_rn(v);
    }
}

// ---------------------------------------------------------------------------
// Selective scan
// ---------------------------------------------------------------------------
__global__ __launch_bounds__(128) void scan_kernel(
    const float* __restrict__ dt,
    const float* __restrict__ z,
    const float* __restrict__ xdbl,
    const float* __restrict__ A_log,
    const float* __restrict__ D_skip,
    __half* __restrict__ y16)
{
    const int gid = blockIdx.x * blockDim.x + threadIdx.x;
    const int d = gid >> 4;
    const int s = gid & 15;

    const float Aval = -expf(A_log[d * D_STATE + s]);
    const float Dv = D_skip[d];

    const float* Bp = xdbl + DT_RANK + s;
    const float* Cp = xdbl + DT_RANK + D_STATE + s;

    float h = 0.f;
    #pragma unroll 4
    for (int t = 0; t < LSEQ; t++) {
        const float dtv = dt[(size_t)t * D_INNER + d];
        const float zv  = z [(size_t)t * D_INNER + d];
        const float Bv  = Bp[(size_t)t * XPROJ_N];
        const float Cv  = Cp[(size_t)t * XPROJ_N];

        const float abar = __expf(dtv * Aval);
        h = fmaf(abar, h, dtv * zv * Bv);

        float p = h * Cv;
        p += __shfl_xor_sync(0xffffffffu, p, 8);
        p += __shfl_xor_sync(0xffffffffu, p, 4);
        p += __shfl_xor_sync(0xffffffffu, p, 2);
        p += __shfl_xor_sync(0xffffffffu, p, 1);
        if (s == 0)
            y16[(size_t)t * D_INNER + d] = __float2half_rn(p + Dv * zv);
    }
}

// ---------------------------------------------------------------------------
// Launch
// ---------------------------------------------------------------------------
#define SMEM128 (3 * (128 * 128 + 128 * 128))   // 98304; epilogue needs 67584
#define SMEM64  (3 * (64 * 128 + 128 * 128))    // 73728; epilogue needs 33792

extern "C" void kernel_launch(void* const* d_in, const int* in_sizes, int n_in,
                              void* d_out, int out_size)
{
    const float* x        = (const float*)d_in[0];
    const float* w_norm1  = (const float*)d_in[1];
    const float* W_in     = (const float*)d_in[2];
    const float* W_gate   = (const float*)d_in[3];
    const float* W_xproj  = (const float*)d_in[4];
    const float* W_dt     = (const float*)d_in[5];
    const float* b_dt     = (const float*)d_in[6];
    const float* A_log    = (const float*)d_in[7];
    const float* D_skip   = (const float*)d_in[8];
    const float* W_out    = (const float*)d_in[9];
    const float* w_ffn    = (const float*)d_in[10];
    const float* W_up     = (const float*)d_in[11];
    const float* W_gate_f = (const float*)d_in[12];
    const float* W_down   = (const float*)d_in[13];
    float* out = (float*)d_out;

    float *p_lin1, *p_lin2, *p_xdbl, *p_dt, *p_x2, *p_up, *p_gate;
    cudaGetSymbolAddress((void**)&p_lin1, g_lin1);
    cudaGetSymbolAddress((void**)&p_lin2, g_lin2);
    cudaGetSymbolAddress((void**)&p_xdbl, g_xdbl);
    cudaGetSymbolAddress((void**)&p_dt,   g_dt);
    cudaGetSymbolAddress((void**)&p_x2,   g_x2);
    cudaGetSymbolAddress((void**)&p_up,   g_up);
    cudaGetSymbolAddress((void**)&p_gate, g_gate);

    __half *hA,*zA,*xdA,*yA,*hfA,*vA;
    cudaGetSymbolAddress((void**)&hA,  a_h);
    cudaGetSymbolAddress((void**)&zA,  a_z);
    cudaGetSymbolAddress((void**)&xdA, a_xd);
    cudaGetSymbolAddress((void**)&yA,  a_y);
    cudaGetSymbolAddress((void**)&hfA, a_hf);
    cudaGetSymbolAddress((void**)&vA,  a_v);

    __half *winH,*wgtH,*wxH,*wdtH,*woH,*wuH,*wgfH,*wdnH;
    cudaGetSymbolAddress((void**)&winH, w_in_h);
    cudaGetSymbolAddress((void**)&wgtH, w_gt_h);
    cudaGetSymbolAddress((void**)&wxH,  w_x_h);
    cudaGetSymbolAddress((void**)&wdtH, w_dt_h);
    cudaGetSymbolAddress((void**)&woH,  w_out_h);
    cudaGetSymbolAddress((void**)&wuH,  w_up_h);
    cudaGetSymbolAddress((void**)&wgfH, w_gf_h);
    cudaGetSymbolAddress((void**)&wdnH, w_dn_h);

    cudaFuncSetAttribute(gemm_h1<128>, cudaFuncAttributeMaxDynamicSharedMemorySize, SMEM128);
    cudaFuncSetAttribute(gemm_h1<64>,  cudaFuncAttributeMaxDynamicSharedMemorySize, SMEM64);

    const dim3 blk(256);

    w16_all_kernel<<<(SEG6 + 255) / 256, blk>>>(
        W_in, winH, W_gate, wgtH, W_xproj, wxH, W_out, woH,
        W_up, wuH, W_gate_f, wgfH, W_down, wdnH);
    w16_wdt_kernel<<<(D_INNER * KDT_PAD + 255) / 256, blk>>>(W_dt, wdtH);

    // 1) h = rmsnorm(x)
    rmsnorm_kernel<<<LSEQ, blk>>>(x, w_norm1, hA);

    // 2+3) lin1 = h @ W_in^T ; lin2 = h @ W_gate^T  (batched raw fp32)
    gemm_h1<128><<<dim3(D_INNER / 128, LSEQ / 128, 2), blk, SMEM128>>>(
        hA, winH, wgtH, D_MODEL, D_INNER,
        p_lin1, p_lin2, nullptr, nullptr, nullptr, 0);

    // z = lin1 * sigmoid(lin2)
    gate_kernel<<<(LSEQ * D_INNER / 4 + 255) / 256, blk>>>(
        p_lin1, p_lin2, zA, LSEQ * D_INNER / 4);

    // 4) xdbl = z @ W_xproj^T (split-K = 4, atomic accumulate)
    cudaMemsetAsync(p_xdbl, 0, (size_t)LSEQ * XPROJ_N * sizeof(float));
    gemm_h1<64><<<dim3(XPROJ_N / 128, LSEQ / 64, 4), blk, SMEM64>>>(
        zA, wxH, nullptr, D_INNER, XPROJ_N,
        p_xdbl, nullptr, nullptr, nullptr, nullptr, 5);
    cvt16_kernel<<<(LSEQ * XPROJ_N / 4 + 255) / 256, blk>>>(
        p_xdbl, xdA, LSEQ * XPROJ_N / 4);

    // 5) dt = softplus(xdbl @ W_dt_pad^T + b_dt)
    gemm_h1<128><<<dim3(D_INNER / 128, LSEQ / 128), blk, SMEM128>>>(
        xdA, wdtH, nullptr, KDT_PAD, D_INNER,
        p_dt, nullptr, nullptr, nullptr, b_dt, 1);

    // 6) scan
    scan_kernel<<<(D_INNER * D_STATE) / 128, dim3(128)>>>(
        p_dt, p_lin1, p_xdbl, A_log, D_skip, yA);

    // 7) x2 = x + y @ W_out^T
    gemm_h1<64><<<dim3(D_MODEL / 128, LSEQ / 64), blk, SMEM64>>>(
        yA, woH, nullptr, D_INNER, D_MODEL,
        p_x2, nullptr, nullptr, x, nullptr, 3);

    // 8) hf = rmsnorm(x2)
    rmsnorm_kernel<<<LSEQ, blk>>>(p_x2, w_ffn, hfA);

    // 9+10a) up / gate (batched raw)
    gemm_h1<128><<<dim3(H_FFN / 128, LSEQ / 128, 2), blk, SMEM128>>>(
        hfA, wuH, wgfH, D_MODEL, H_FFN,
        p_up, p_gate, nullptr, nullptr, nullptr, 0);

    // 10b) v = silu(gate) * up
    silu_mul_kernel<<<(LSEQ * H_FFN / 4 + 255) / 256, blk>>>(
        p_up, p_gate, vA, LSEQ * H_FFN / 4);

    // 11) out = x2 + v @ W_down^T
    gemm_h1<64><<<dim3(D_MODEL / 128, LSEQ / 64), blk, SMEM64>>>(
        vA, wdnH, nullptr, H_FFN, D_MODEL,
        out, nullptr, nullptr, p_x2, nullptr, 3);
}

// round 10
// speedup vs baseline: 1.0823x; 1.0823x over previous
#include <cuda_runtime.h>
#include <cuda_fp16.h>
#include <math.h>
#include <stdint.h>

// ---------------------------------------------------------------------------
// Problem dims
// ---------------------------------------------------------------------------
#define D_MODEL 768
#define D_INNER 1536
#define D_STATE 16
#define DT_RANK 96
#define H_FFN   2048
#define LSEQ    2048
#define XPROJ_N 128
#define KDT_PAD 128

// ---------------------------------------------------------------------------
// Scratch
// ---------------------------------------------------------------------------
__device__ float g_lin1[LSEQ * D_INNER];   // raw in-proj, then z (in-place)
__device__ float g_lin2[LSEQ * D_INNER];   // raw gate-proj
__device__ float g_xdbl[LSEQ * XPROJ_N];
__device__ float g_dt  [LSEQ * D_INNER];
__device__ float g_x2  [LSEQ * D_MODEL];
__device__ float g_up  [LSEQ * H_FFN];
__device__ float g_gate[LSEQ * H_FFN];

// fp16 activations
__device__ __half a_h  [LSEQ * D_MODEL];
__device__ __half a_z  [LSEQ * D_INNER];
__device__ __half a_xd [LSEQ * XPROJ_N];
__device__ __half a_y  [LSEQ * D_INNER];
__device__ __half a_hf [LSEQ * D_MODEL];
__device__ __half a_v  [LSEQ * H_FFN];

// fp16 weights
__device__ __half w_in_h [D_INNER * D_MODEL];
__device__ __half w_gt_h [D_INNER * D_MODEL];
__device__ __half w_x_h  [XPROJ_N * D_INNER];
__device__ __half w_dt_h [D_INNER * KDT_PAD];
__device__ __half w_out_h[D_MODEL * D_INNER];
__device__ __half w_up_h [H_FFN * D_MODEL];
__device__ __half w_gf_h [H_FFN * D_MODEL];
__device__ __half w_dn_h [D_MODEL * H_FFN];

static __device__ __forceinline__ uint32_t smem_u32(const void* p) {
    uint32_t a;
    asm("{ .reg .u64 t; cvta.to.shared.u64 t, %1; cvt.u32.u64 %0, t; }"
        : "=r"(a) : "l"(p));
    return a;
}

#define SW128(off) ((off) ^ (((off) >> 3) & 0x70))

#define LDSM4(r, addr)                                                         \
    asm volatile("ldmatrix.sync.aligned.m8n8.x4.shared.b16 {%0,%1,%2,%3}, [%4];" \
        : "=r"((r)[0]), "=r"((r)[1]), "=r"((r)[2]), "=r"((r)[3]) : "r"(addr))

#define MMA16816(c, a, b0, b1)                                                 \
    asm volatile("mma.sync.aligned.m16n8k16.row.col.f32.f16.f16.f32 "          \
        "{%0,%1,%2,%3}, {%4,%5,%6,%7}, {%8,%9}, {%0,%1,%2,%3};"                \
        : "+f"((c)[0]), "+f"((c)[1]), "+f"((c)[2]), "+f"((c)[3])               \
        : "r"((a)[0]), "r"((a)[1]), "r"((a)[2]), "r"((a)[3]), "r"(b0), "r"(b1))

#define CP_ASYNC16(sa, ga)                                                     \
    asm volatile("{ .reg .u64 g; cvta.to.global.u64 g, %1; "                   \
                 "cp.async.cg.shared.global [%0], [g], 16; }"                  \
                 :: "r"(sa), "l"(ga))
#define CP_COMMIT()  asm volatile("cp.async.commit_group;" ::: "memory")
#define CP_WAIT1()   asm volatile("cp.async.wait_group 1;" ::: "memory")

// ---------------------------------------------------------------------------
// All-weights fp32->fp16 convert, one launch, compile-time segments (float4)
// ---------------------------------------------------------------------------
#define N_IN  (D_INNER * D_MODEL)
#define N_X   (XPROJ_N * D_INNER)
#define N_OUT (D_MODEL * D_INNER)
#define N_UP  (H_FFN * D_MODEL)
#define N_DN  (D_MODEL * H_FFN)
#define Q4(n) ((n) / 4)
#define SEG0 Q4(N_IN)
#define SEG1 (SEG0 + Q4(N_IN))
#define SEG2 (SEG1 + Q4(N_X))
#define SEG3 (SEG2 + Q4(N_OUT))
#define SEG4 (SEG3 + Q4(N_UP))
#define SEG5 (SEG4 + Q4(N_UP))
#define SEG6 (SEG5 + Q4(N_DN))

__global__ void w16_all_kernel(
    const float* __restrict__ sin,  __half* __restrict__ din,
    const float* __restrict__ sgt,  __half* __restrict__ dgt,
    const float* __restrict__ sx,   __half* __restrict__ dx,
    const float* __restrict__ sout, __half* __restrict__ dout,
    const float* __restrict__ sup,  __half* __restrict__ dup,
    const float* __restrict__ sgf,  __half* __restrict__ dgf,
    const float* __restrict__ sdn,  __half* __restrict__ ddn)
{
    int i = blockIdx.x * blockDim.x + threadIdx.x;
    if (i >= SEG6) return;
    const float* s; __half* d; int b;
    if      (i < SEG0) { s = sin;  d = din;  b = i; }
    else if (i < SEG1) { s = sgt;  d = dgt;  b = i - SEG0; }
    else if (i < SEG2) { s = sx;   d = dx;   b = i - SEG1; }
    else if (i < SEG3) { s = sout; d = dout; b = i - SEG2; }
    else if (i < SEG4) { s = sup;  d = dup;  b = i - SEG3; }
    else if (i < SEG5) { s = sgf;  d = dgf;  b = i - SEG4; }
    else               { s = sdn;  d = ddn;  b = i - SEG5; }
    float4 v = reinterpret_cast<const float4*>(s)[b];
    __half2* o = reinterpret_cast<__half2*>(d) + b * 2;
    o[0] = __floats2half2_rn(v.x, v.y);
    o[1] = __floats2half2_rn(v.z, v.w);
}

__global__ void w16_wdt_kernel(const float* __restrict__ src,
                               __half* __restrict__ dst)
{
    int i = blockIdx.x * blockDim.x + threadIdx.x;
    if (i < D_INNER * KDT_PAD) {
        int r = i / KDT_PAD, c = i % KDT_PAD;
        float v = (c < DT_RANK) ? src[r * DT_RANK + c] : 0.f;
        dst[i] = __float2half_rn(v);
    }
}

// ---------------------------------------------------------------------------
// Elementwise
// ---------------------------------------------------------------------------
__global__ void gate_kernel(float* __restrict__ lin1,
                            const float* __restrict__ lin2,
                            __half* __restrict__ zh, int n4)
{
    int i = blockIdx.x * blockDim.x + threadIdx.x;
    if (i < n4) {
        float4 a = reinterpret_cast<float4*>(lin1)[i];
        float4 g = reinterpret_cast<const float4*>(lin2)[i];
        a.x *= 1.f / (1.f + __expf(-g.x));
        a.y *= 1.f / (1.f + __expf(-g.y));
        a.z *= 1.f / (1.f + __expf(-g.z));
        a.w *= 1.f / (1.f + __expf(-g.w));
        reinterpret_cast<float4*>(lin1)[i] = a;
        __half2* o = reinterpret_cast<__half2*>(zh) + i * 2;
        o[0] = __floats2half2_rn(a.x, a.y);
        o[1] = __floats2half2_rn(a.z, a.w);
    }
}

__global__ void silu_mul_kernel(const float* __restrict__ up,
                                const float* __restrict__ gate,
                                __half* __restrict__ vh, int n4)
{
    int i = blockIdx.x * blockDim.x + threadIdx.x;
    if (i < n4) {
        float4 u = reinterpret_cast<const float4*>(up)[i];
        float4 g = reinterpret_cast<const float4*>(gate)[i];
        float4 v;
        v.x = g.x / (1.f + __expf(-g.x)) * u.x;
        v.y = g.y / (1.f + __expf(-g.y)) * u.y;
        v.z = g.z / (1.f + __expf(-g.z)) * u.z;
        v.w = g.w / (1.f + __expf(-g.w)) * u.w;
        __half2* o = reinterpret_cast<__half2*>(vh) + i * 2;
        o[0] = __floats2half2_rn(v.x, v.y);
        o[1] = __floats2half2_rn(v.z, v.w);
    }
}

__global__ void cvt16_kernel(const float* __restrict__ src,
                             __half* __restrict__ dst, int n4)
{
    int i = blockIdx.x * blockDim.x + threadIdx.x;
    if (i < n4) {
        float4 v = reinterpret_cast<const float4*>(src)[i];
        __half2* o = reinterpret_cast<__half2*>(dst) + i * 2;
        o[0] = __floats2half2_rn(v.x, v.y);
        o[1] = __floats2half2_rn(v.z, v.w);
    }
}

// ---------------------------------------------------------------------------
// RMSNorm -> fp16
// ---------------------------------------------------------------------------
__global__ __launch_bounds__(256) void rmsnorm_kernel(
    const float* __restrict__ x, const float* __restrict__ w,
    __half* __restrict__ o16)
{
    const int t = blockIdx.x;
    const float* xr = x + (size_t)t * D_MODEL;

    float ss = 0.f;
    for (int i = threadIdx.x; i < D_MODEL; i += 256) {
        float v = xr[i];
        ss = fmaf(v, v, ss);
    }
    #pragma unroll
    for (int o = 16; o > 0; o >>= 1) ss += __shfl_xor_sync(0xffffffffu, ss, o);

    __shared__ float sh[8];
    __shared__ float s_rs;
    const int lane = threadIdx.x & 31, wid = threadIdx.x >> 5;
    if (lane == 0) sh[wid] = ss;
    __syncthreads();
    if (threadIdx.x == 0) {
        float tot = 0.f;
        #pragma unroll
        for (int i = 0; i < 8; i++) tot += sh[i];
        s_rs = rsqrtf(tot * (1.0f / D_MODEL) + 1e-6f);
    }
    __syncthreads();
    const float rs = s_rs;
    for (int i = threadIdx.x; i < D_MODEL; i += 256)
        o16[(size_t)t * D_MODEL + i] = __float2half_rn(xr[i] * rs * w[i]);
}

// ---------------------------------------------------------------------------
// fp16 GEMM on mma.sync: C[M,N] = f(A[M,K] @ B[N,K]^T), fp32 accumulate.
//   BM in {128, 64}; BN=128, KC=64, 256 threads, 3-stage cp.async pipeline,
//   one __syncthreads per chunk. __launch_bounds__(256,2) pins regs <= 128
//   so 2 CTAs stay resident per SM (the R8 regression was regs=134 -> 1 CTA).
//   op: 0 none | 1 bias+softplus | 3 acc+aux | 5 split-K atomicAdd
//   op!=5: gridDim.z==2 batches second (B2, out2) GEMM sharing A.
// ---------------------------------------------------------------------------
template<int BM>
__global__ __launch_bounds__(256, 2) void gemm_h1(
    const __half* __restrict__ Ah,
    const __half* __restrict__ Bh_, const __half* __restrict__ B2h,
    int K, int N,
    float* __restrict__ outF_, float* __restrict__ out2F,
    __half* __restrict__ outH,
    const float* __restrict__ aux, const float* __restrict__ bias, int op)
{
    constexpr int WN  = (BM == 128) ? 2 : 4;
    constexpr int NT  = 128 / WN / 8;            // 8 or 4
    constexpr int ATB = BM * 128;                // BM rows x 64 halves x 2B
    constexpr int BTB = 128 * 128;
    constexpr int STAGE_B = ATB + BTB;

    const bool batched2 = (op != 5) && (blockIdx.z != 0);
    const __half* Bh = batched2 ? B2h : Bh_;
    float* outF = batched2 ? out2F : outF_;

    int k_begin = 0, KL = K;
    if (op == 5) { KL = K / gridDim.z; k_begin = blockIdx.z * KL; }

    extern __shared__ char smem[];
    const uint32_t sb = smem_u32(smem);
    const int tid  = threadIdx.x;
    const int lane = tid & 31;
    const int warp = tid >> 5;
    const int m0 = blockIdx.y * BM;
    const int n0 = blockIdx.x * 128;
    const int wm0 = (warp / WN) * 32;
    const int wn0 = (warp % WN) * (128 / WN);

    const int nch = KL >> 6;

    float acc[2][NT][4];
    #pragma unroll
    for (int mt = 0; mt < 2; mt++)
        #pragma unroll
        for (int nt = 0; nt < NT; nt++)
            #pragma unroll
            for (int r = 0; r < 4; r++) acc[mt][nt][r] = 0.f;

    auto load_stage = [&](int s, int ci) {
        const int k0 = k_begin + (ci << 6);
        const uint32_t sbase = sb + s * STAGE_B;
        #pragma unroll
        for (int arr = 0; arr < 2; arr++) {
            const __half* src = (arr == 0) ? Ah : Bh;
            const int r0 = (arr == 0) ? m0 : n0;
            const int nvec = ((arr == 0) ? BM : 128) * 8;
            const uint32_t abase = sbase + ((arr == 0) ? 0 : ATB);
            #pragma unroll
            for (int jj = 0; jj < nvec / 256; jj++) {
                const int idx = jj * 256 + tid;
                const int row = idx >> 3;
                const int c16 = idx & 7;
                const __half* g = src + (size_t)(r0 + row) * K + k0 + c16 * 8;
                const uint32_t sa = abase + SW128((uint32_t)(row * 128 + c16 * 16));
                CP_ASYNC16(sa, g);
            }
        }
    };

    const int arow = ((lane >> 3) & 1) * 8 + (lane & 7);
    const int akb  = (lane >> 4) * 16;
    const int brow = ((lane >> 4) & 1) * 8 + (lane & 7);
    const int bkb  = ((lane >> 3) & 1) * 16;

    auto compute = [&](int s) {
        const uint32_t sA = sb + s * STAGE_B;
        const uint32_t sB = sA + ATB;
        #pragma unroll
        for (int ks = 0; ks < 4; ks++) {
            uint32_t a_h[2][4], b_h[NT / 2][4];
            #pragma unroll
            for (int mt = 0; mt < 2; mt++) {
                const uint32_t off = SW128(
                    (uint32_t)((wm0 + mt * 16 + arow) * 128 + ks * 32 + akb));
                LDSM4(a_h[mt], sA + off);
            }
            #pragma unroll
            for (int j = 0; j < NT / 2; j++) {
                const uint32_t off = SW128(
                    (uint32_t)((wn0 + j * 16 + brow) * 128 + ks * 32 + bkb));
                LDSM4(b_h[j], sB + off);
            }
            #pragma unroll
            for (int mt = 0; mt < 2; mt++)
                #pragma unroll
                for (int nt = 0; nt < NT; nt++) {
                    const uint32_t bh0 = b_h[nt >> 1][(nt & 1) * 2];
                    const uint32_t bh1 = b_h[nt >> 1][(nt & 1) * 2 + 1];
                    MMA16816(acc[mt][nt], a_h[mt], bh0, bh1);
                }
        }
    };

    // ---- 3-stage pipeline, one sync per chunk ----
    load_stage(0, 0); CP_COMMIT();
    if (nch > 1) { load_stage(1, 1); CP_COMMIT(); }
    int cs = 0, ls = 2;
    for (int i = 0; i < nch; i++) {
        CP_WAIT1();
        __syncthreads();
        if (i + 2 < nch) {
            load_stage(ls, i + 2); CP_COMMIT();
            ls = (ls == 2) ? 0 : ls + 1;
        }
        compute(cs);
        cs = (cs == 2) ? 0 : cs + 1;
    }
    __syncthreads();

    // epilogue via smem for coalesced stores
    float* smC = reinterpret_cast<float*>(smem);   // [BM][132]
    #pragma unroll
    for (int mt = 0; mt < 2; mt++)
        #pragma unroll
        for (int nt = 0; nt < NT; nt++) {
            const int row = wm0 + mt * 16 + (lane >> 2);
            const int col = wn0 + nt * 8 + (lane & 3) * 2;
            *reinterpret_cast<float2*>(&smC[row * 132 + col]) =
                make_float2(acc[mt][nt][0], acc[mt][nt][1]);
            *reinterpret_cast<float2*>(&smC[(row + 8) * 132 + col]) =
                make_float2(acc[mt][nt][2], acc[mt][nt][3]);
        }
    __syncthreads();

    #pragma unroll 4
    for (int e = tid; e < BM * 128; e += 256) {
        const int row = e >> 7, col = e & 127;
        float v = smC[row * 132 + col];
        const size_t ro = (size_t)(m0 + row) * N + (n0 + col);
        if (op == 1) {
            v += bias[n0 + col];
            v = (v > 20.f) ? v : log1pf(__expf(v));
        } else if (op == 3) {
            v += aux[ro];
        } else if (op == 5) {
            atomicAdd(&outF[ro], v);
            continue;
        }
        if (outF) outF[ro] = v;
        if (outH) outH[ro] = __float2half_rn(v);
    }
}

// ---------------------------------------------------------------------------
// Selective scan
// ---------------------------------------------------------------------------
__global__ __launch_bounds__(128) void scan_kernel(
    const float* __restrict__ dt,
    const float* __restrict__ z,
    const float* __restrict__ xdbl,
    const float* __restrict__ A_log,
    const float* __restrict__ D_skip,
    __half* __restrict__ y16)
{
    const int gid = blockIdx.x * blockDim.x + threadIdx.x;
    const int d = gid >> 4;
    const int s = gid & 15;

    const float Aval = -expf(A_log[d * D_STATE + s]);
    const float Dv = D_skip[d];

    const float* Bp = xdbl + DT_RANK + s;
    const float* Cp = xdbl + DT_RANK + D_STATE + s;

    float h = 0.f;
    #pragma unroll 4
    for (int t = 0; t < LSEQ; t++) {
        const float dtv = dt[(size_t)t * D_INNER + d];
        const float zv  = z [(size_t)t * D_INNER + d];
        const float Bv  = Bp[(size_t)t * XPROJ_N];
        const float Cv  = Cp[(size_t)t * XPROJ_N];

        const float abar = __expf(dtv * Aval);
        h = fmaf(abar, h, dtv * zv * Bv);

        float p = h * Cv;
        p += __shfl_xor_sync(0xffffffffu, p, 8);
        p += __shfl_xor_sync(0xffffffffu, p, 4);
        p += __shfl_xor_sync(0xffffffffu, p, 2);
        p += __shfl_xor_sync(0xffffffffu, p, 1);
        if (s == 0)
            y16[(size_t)t * D_INNER + d] = __float2half_rn(p + Dv * zv);
    }
}

// ---------------------------------------------------------------------------
// Launch
// ---------------------------------------------------------------------------
#define SMEM128 (3 * (128 * 128 + 128 * 128))   // 98304; epilogue needs 67584
#define SMEM64  (3 * (64 * 128 + 128 * 128))    // 73728; epilogue needs 33792

extern "C" void kernel_launch(void* const* d_in, const int* in_sizes, int n_in,
                              void* d_out, int out_size)
{
    const float* x        = (const float*)d_in[0];
    const float* w_norm1  = (const float*)d_in[1];
    const float* W_in     = (const float*)d_in[2];
    const float* W_gate   = (const float*)d_in[3];
    const float* W_xproj  = (const float*)d_in[4];
    const float* W_dt     = (const float*)d_in[5];
    const float* b_dt     = (const float*)d_in[6];
    const float* A_log    = (const float*)d_in[7];
    const float* D_skip   = (const float*)d_in[8];
    const float* W_out    = (const float*)d_in[9];
    const float* w_ffn    = (const float*)d_in[10];
    const float* W_up     = (const float*)d_in[11];
    const float* W_gate_f = (const float*)d_in[12];
    const float* W_down   = (const float*)d_in[13];
    float* out = (float*)d_out;

    float *p_lin1, *p_lin2, *p_xdbl, *p_dt, *p_x2, *p_up, *p_gate;
    cudaGetSymbolAddress((void**)&p_lin1, g_lin1);
    cudaGetSymbolAddress((void**)&p_lin2, g_lin2);
    cudaGetSymbolAddress((void**)&p_xdbl, g_xdbl);
    cudaGetSymbolAddress((void**)&p_dt,   g_dt);
    cudaGetSymbolAddress((void**)&p_x2,   g_x2);
    cudaGetSymbolAddress((void**)&p_up,   g_up);
    cudaGetSymbolAddress((void**)&p_gate, g_gate);

    __half *hA,*zA,*xdA,*yA,*hfA,*vA;
    cudaGetSymbolAddress((void**)&hA,  a_h);
    cudaGetSymbolAddress((void**)&zA,  a_z);
    cudaGetSymbolAddress((void**)&xdA, a_xd);
    cudaGetSymbolAddress((void**)&yA,  a_y);
    cudaGetSymbolAddress((void**)&hfA, a_hf);
    cudaGetSymbolAddress((void**)&vA,  a_v);

    __half *winH,*wgtH,*wxH,*wdtH,*woH,*wuH,*wgfH,*wdnH;
    cudaGetSymbolAddress((void**)&winH, w_in_h);
    cudaGetSymbolAddress((void**)&wgtH, w_gt_h);
    cudaGetSymbolAddress((void**)&wxH,  w_x_h);
    cudaGetSymbolAddress((void**)&wdtH, w_dt_h);
    cudaGetSymbolAddress((void**)&woH,  w_out_h);
    cudaGetSymbolAddress((void**)&wuH,  w_up_h);
    cudaGetSymbolAddress((void**)&wgfH, w_gf_h);
    cudaGetSymbolAddress((void**)&wdnH, w_dn_h);

    cudaFuncSetAttribute(gemm_h1<128>, cudaFuncAttributeMaxDynamicSharedMemorySize, SMEM128);
    cudaFuncSetAttribute(gemm_h1<64>,  cudaFuncAttributeMaxDynamicSharedMemorySize, SMEM64);

    const dim3 blk(256);

    w16_all_kernel<<<(SEG6 + 255) / 256, blk>>>(
        W_in, winH, W_gate, wgtH, W_xproj, wxH, W_out, woH,
        W_up, wuH, W_gate_f, wgfH, W_down, wdnH);
    w16_wdt_kernel<<<(D_INNER * KDT_PAD + 255) / 256, blk>>>(W_dt, wdtH);

    // 1) h = rmsnorm(x)
    rmsnorm_kernel<<<LSEQ, blk>>>(x, w_norm1, hA);

    // 2+3) lin1 = h @ W_in^T ; lin2 = h @ W_gate^T  (batched raw fp32)
    gemm_h1<128><<<dim3(D_INNER / 128, LSEQ / 128, 2), blk, SMEM128>>>(
        hA, winH, wgtH, D_MODEL, D_INNER,
        p_lin1, p_lin2, nullptr, nullptr, nullptr, 0);

    // z = lin1 * sigmoid(lin2)
    gate_kernel<<<(LSEQ * D_INNER / 4 + 255) / 256, blk>>>(
        p_lin1, p_lin2, zA, LSEQ * D_INNER / 4);

    // 4) xdbl = z @ W_xproj^T (split-K = 4, atomic accumulate)
    cudaMemsetAsync(p_xdbl, 0, (size_t)LSEQ * XPROJ_N * sizeof(float));
    gemm_h1<64><<<dim3(XPROJ_N / 128, LSEQ / 64, 4), blk, SMEM64>>>(
        zA, wxH, nullptr, D_INNER, XPROJ_N,
        p_xdbl, nullptr, nullptr, nullptr, nullptr, 5);
    cvt16_kernel<<<(LSEQ * XPROJ_N / 4 + 255) / 256, blk>>>(
        p_xdbl, xdA, LSEQ * XPROJ_N / 4);

    // 5) dt = softplus(xdbl @ W_dt_pad^T + b_dt)
    gemm_h1<128><<<dim3(D_INNER / 128, LSEQ / 128), blk, SMEM128>>>(
        xdA, wdtH, nullptr, KDT_PAD, D_INNER,
        p_dt, nullptr, nullptr, nullptr, b_dt, 1);

    // 6) scan
    scan_kernel<<<(D_INNER * D_STATE) / 128, dim3(128)>>>(
        p_dt, p_lin1, p_xdbl, A_log, D_skip, yA);

    // 7) x2 = x + y @ W_out^T
    gemm_h1<64><<<dim3(D_MODEL / 128, LSEQ / 64), blk, SMEM64>>>(
        yA, woH, nullptr, D_INNER, D_MODEL,
        p_x2, nullptr, nullptr, x, nullptr, 3);

    // 8) hf = rmsnorm(x2)
    rmsnorm_kernel<<<LSEQ, blk>>>(p_x2, w_ffn, hfA);

    // 9+10a) up / gate (batched raw)
    gemm_h1<128><<<dim3(H_FFN / 128, LSEQ / 128, 2), blk, SMEM128>>>(
        hfA, wuH, wgfH, D_MODEL, H_FFN,
        p_up, p_gate, nullptr, nullptr, nullptr, 0);

    // 10b) v = silu(gate) * up
    silu_mul_kernel<<<(LSEQ * H_FFN / 4 + 255) / 256, blk>>>(
        p_up, p_gate, vA, LSEQ * H_FFN / 4);

    // 11) out = x2 + v @ W_down^T
    gemm_h1<64><<<dim3(D_MODEL / 128, LSEQ / 64), blk, SMEM64>>>(
        vA, wdnH, nullptr, H_FFN, D_MODEL,
        out, nullptr, nullptr, p_x2, nullptr, 3);
}